// round 16
// baseline (speedup 1.0000x reference)
#include <cuda_runtime.h>
#include <cuda_bf16.h>
#include <cstdint>

// Problem constants
#define S_      128      // seq_len
#define NBITS   256      // bits per token / neurons per head (B)
#define NHEAD   16       // heads (H)
#define NB_     12       // bits per neuron (LUT address width)
#define LUTW    128      // 2^12 / 32 words
#define NSLOT   4        // heads processed concurrently per CTA
#define THREADS 512      // NSLOT * 128
#define NUNIT   16       // 4 CTAs x 4 slots finishing units per column

// ---------------- scratch (__device__ globals; no allocation) ----------------
__device__ uint32_t g_tokbits[8 * S_];      // 4 KB packed tokens: [w][i] bit l = tokens[i][32w+l]
__device__ int      g_cnt[NBITS * S_];      // 128 KB per-(n,i) head-parity counts (self-cleaned)
__device__ int      g_tick[NBITS];          // per-column finishing tickets (self-cleaned)

// ============================================================================
// Kernel 0: pack tokens via ballot. grid=32 x 256 -> 256 warps, 4 words each.
// ============================================================================
__global__ void pack_tokens_k(const int* __restrict__ tokens) {
    const int lane = threadIdx.x & 31;
    const int gw   = blockIdx.x * 8 + (threadIdx.x >> 5);   // 0..255
#pragma unroll
    for (int k = 0; k < 4; k++) {
        int m  = gw * 4 + k;                                // 0..1023
        int tk = m >> 3, w = m & 7;
        int v = tokens[tk * NBITS + w * 32 + lane];         // 128B coalesced
        uint32_t b = __ballot_sync(0xffffffffu, v != 0);
        if (lane == 0) g_tokbits[w * S_ + tk] = b;
    }
}

// ============================================================================
// Kernel 1: main + slot-autonomous vote. grid = 1024 = (hg) x (n); block = 512
// = 4 independent slots of 128 threads. Slot g -> head h = hg*4+g.
//   addr(i,j) = aq[i] | ak[j] | ap[i-j]   (disjoint bit positions)
// Stage D tiles the causal triangle into 20 subtiles (32 rows x 16 keys):
//   row-group rg (rows 32rg..32rg+31), key-block kb (keys 16kb..16kb+15),
//   kb <= 2rg+1. Warp wl statically takes subtiles s = 4k+wl (k=0..4):
//   exactly 5 subtiles AND exactly 2064 active keys per warp (perfect balance).
// Within a subtile: lane = row (stride-1 aq/ap, conflict-free), j uniform
// (broadcast ak). Row partials combine via conflict-free shared atomicXor.
// ============================================================================
__global__ void __launch_bounds__(THREADS, 4)
softram_main_k(const float* __restrict__ mem, const int* __restrict__ conn,
               float* __restrict__ out) {
    __shared__ uint32_t s_tok[8 * S_];                       // 4 KB token bitset
    __shared__ uint32_t s_lut[NSLOT][LUTW];                  // 2 KB per-slot LUT bits
    __shared__ uint32_t s_ak [NSLOT][S_];                    // key-j contribution
    __shared__ uint32_t s_ap [NSLOT][S_];                    // distance-d contribution
    __shared__ uint32_t s_aq [NSLOT][S_];                    // per-row query contribution
    __shared__ uint32_t s_par[NSLOT][S_];                    // per-row parity accumulators
    __shared__ int      s_flag[NSLOT];

    const int bid  = blockIdx.x;
    const int n    = bid & (NBITS - 1);                      // 0..255
    const int hg   = bid >> 8;                               // 0..3
    const int t    = threadIdx.x;
    const int lane = t & 31;
    const int g    = t >> 7;                                 // slot 0..3
    const int i    = t & 127;                                // row index for setup/epilogue
    const int wl   = (t >> 5) & 3;                           // warp within slot

    const int h  = hg * NSLOT + g;
    const int hn = h * NBITS + n;

    // ---- Stage A: stage packed tokens; the only block-wide sync ----
    s_tok[t]       = g_tokbits[t];
    s_tok[t + 512] = g_tokbits[t + 512];
    __syncthreads();

    // ---- Stage B: binarize this head's 4096-float LUT slice (slot's 4 warps) ----
    {
        const float* mb = mem + (size_t)hn * 4096;
#pragma unroll
        for (int m = wl; m < LUTW; m += 4) {
            float v = mb[m * 32 + lane];                     // 128B coalesced
            uint32_t b = __ballot_sync(0xffffffffu, v > 0.0f);
            if (lane == 0) s_lut[g][m] = b;
        }
    }

    // ---- Stage C: split the 12 wired connections (uniform within slot) ----
    uint32_t aq = 0, ak = 0, ap = 0;
    bool anyp = false;
#pragma unroll
    for (int b = 0; b < NB_; b++) {
        int c = conn[hn * NB_ + b];                          // uniform load
        if (c < NBITS) {                                     // query bit: tokens[i][c]
            aq |= ((s_tok[(c >> 5) * S_ + i] >> (c & 31)) & 1u) << b;
        } else if (c < 2 * NBITS) {                          // key bit: tokens[j][c-256] (i plays j)
            int c2 = c - NBITS;
            ak |= ((s_tok[(c2 >> 5) * S_ + i] >> (c2 & 31)) & 1u) << b;
        } else {                                             // rel-pos bit p=c-512 (i plays d)
            ap |= (((uint32_t)i >> (c - 2 * NBITS)) & 1u) << b;
            anyp = true;
        }
    }
    s_aq[g][i]  = aq;
    s_ak[g][i]  = ak;
    s_ap[g][i]  = ap;
    s_par[g][i] = 0u;
    asm volatile("bar.sync %0, 128;" :: "r"(g + 1) : "memory");   // slot barrier

    // ---- Stage D: subtile sweep (5 subtiles per warp, statically balanced) ----
    {
        const uint32_t* lutp = s_lut[g];
        const uint32_t* akp  = s_ak[g];
        const uint32_t* app  = s_ap[g];
#pragma unroll 1
        for (int k = 0; k < 5; k++) {
            const int s  = 4 * k + wl;                       // subtile id 0..19
            const int rg = (s < 2) ? 0 : (s < 6) ? 1 : (s < 12) ? 2 : 3;
            const int kb = s - ((rg == 0) ? 0 : (rg == 1) ? 2 : (rg == 2) ? 6 : 12);
            const int row = 32 * rg + lane;                  // lane's row, stride-1
            const uint32_t aqr = s_aq[g][row];               // conflict-free LDS
            const int j0 = 16 * kb;
            const bool diag = (kb >= 2 * rg);                // uniform per warp
            uint32_t acc = 0, acc2 = 0;

            if (!anyp) {
                if (!diag) {                                 // full 32x16 subtile
#pragma unroll
                    for (int jj = 0; jj < 16; jj += 2) {
                        uint32_t a0 = aqr | akp[j0 + jj];
                        uint32_t a1 = aqr | akp[j0 + jj + 1];
                        acc  ^= lutp[a0 >> 5] >> (a0 & 31u);
                        acc2 ^= lutp[a1 >> 5] >> (a1 & 31u);
                    }
                } else {                                     // diagonal: predicate j <= row
#pragma unroll
                    for (int jj = 0; jj < 16; jj++) {
                        int j = j0 + jj;
                        if (j <= row) {
                            uint32_t a = aqr | akp[j];
                            acc ^= lutp[a >> 5] >> (a & 31u);
                        }
                    }
                }
            } else {                                         // pos-wired neuron (~15%)
                if (!diag) {
#pragma unroll
                    for (int jj = 0; jj < 16; jj += 2) {
                        int j = j0 + jj;
                        uint32_t a0 = aqr | akp[j]     | app[row - j];
                        uint32_t a1 = aqr | akp[j + 1] | app[row - j - 1];
                        acc  ^= lutp[a0 >> 5] >> (a0 & 31u);
                        acc2 ^= lutp[a1 >> 5] >> (a1 & 31u);
                    }
                } else {
#pragma unroll
                    for (int jj = 0; jj < 16; jj++) {
                        int j = j0 + jj;
                        if (j <= row) {
                            uint32_t a = aqr | akp[j] | app[row - j];
                            acc ^= lutp[a >> 5] >> (a & 31u);
                        }
                    }
                }
            }
            uint32_t p = (acc ^ acc2) & 1u;
            if (p) atomicXor(&s_par[g][row], 1u);            // stride-1 rows: conflict-free ATOMS
        }
    }
    asm volatile("bar.sync %0, 128;" :: "r"(g + 1) : "memory");

    const uint32_t parity = s_par[g][i] & 1u;

    // ---- Epilogue: slot-autonomous vote (ticket = 16 units per column) ----
    atomicAdd(&g_cnt[n * S_ + i], (int)parity);              // distinct addresses, coalesced
    __threadfence();
    asm volatile("bar.sync %0, 128;" :: "r"(g + 1) : "memory");
    if (i == 0)
        s_flag[g] = (atomicAdd(&g_tick[n], 1) == NUNIT - 1) ? 1 : 0;
    asm volatile("bar.sync %0, 128;" :: "r"(g + 1) : "memory");
    if (s_flag[g]) {                                         // exactly one slot per column
        int sum = atomicExch(&g_cnt[n * S_ + i], 0);         // read + self-clean
        out[i * NBITS + n] = (sum > (NHEAD / 2)) ? 1.0f : 0.0f;
        if (i == 0) g_tick[n] = 0;                           // self-clean ticket
    }
}

// ---------------- launch ----------------
extern "C" void kernel_launch(void* const* d_in, const int* in_sizes, int n_in,
                              void* d_out, int out_size) {
    // Identification proven in R12-R15: exact sizes (elements or bytes),
    // positional fallback in setup_inputs dict order.
    const int*   tokens = (const int*)d_in[0];
    const float* memory = (n_in > 1) ? (const float*)d_in[1] : (const float*)d_in[0];
    const int*   conn   = (n_in > 2) ? (const int*)d_in[2]   : (const int*)d_in[0];
    for (int k = 0; k < n_in && k < 8; k++) {
        long long sz = (long long)in_sizes[k];
        if      (sz == 32768LL    || sz == 131072LL)   tokens = (const int*)d_in[k];
        else if (sz == 16777216LL || sz == 67108864LL) memory = (const float*)d_in[k];
        else if (sz == 49152LL    || sz == 196608LL)   conn   = (const int*)d_in[k];
    }

    pack_tokens_k  <<<32, 256>>>(tokens);
    softram_main_k <<<NSLOT * NBITS, THREADS>>>(memory, conn, (float*)d_out);
    (void)out_size;
}